// round 7
// baseline (speedup 1.0000x reference)
#include <cuda_runtime.h>
#include <math.h>

// ---------------- problem constants ----------------
#define BB    4
#define TT    200
#define HOP   120
#define NN    24000          // T*HOP
#define M1    40
#define A1    5
#define HID   256
#define COND  192
#define NCH   8              // 2B channels (0..3 periodic, 4..7 aperiodic)

#define ALPHA 0.466f
#define AAC   0.782844f      // 1 - ALPHA^2
#define P1C   0.4999273f
#define P2C   0.1067005f
#define P3C   0.00956526f
#define P4C   0.0003041358f
#define SRF   24000.0f

// ---------------- scratch (no allocations allowed) ----------------
__device__ float g_bcoef[NCH * TT * M1];   // MLSA coefficients per channel/frame
__device__ float g_eb0[NCH * TT];          // exp(b[0]) per channel/frame
__device__ float g_b1[NCH * TT];           // b[1] per channel/frame
__device__ float g_f0[BB * TT];            // denormed f0 per batch/frame
__device__ float g_exc[BB * NN];           // periodic excitation (0.5 * pulse)
__device__ float g_wav[NCH * NN];          // per-channel filtered waveform
// tree-scan levels: 24000,12000,6000,3000,1500,750,375,187,93,46,23,11,5,2,1
#define SCAN_TOTAL 47993
__device__ float g_scanbuf[BB * SCAN_TOTAL];

// ==================================================================
// K1: dense frontend: feature embed -> cond -> mel-cepstra -> mc2b
// one block per (b,t) frame
// ==================================================================
__global__ __launch_bounds__(256) void k_frontend(
    const float* __restrict__ mceps, const float* __restrict__ apdcs,
    const float* __restrict__ f0s,
    const float* __restrict__ Wm,  const float* __restrict__ bm,
    const float* __restrict__ Wa,  const float* __restrict__ ba,
    const float* __restrict__ Wf,  const float* __restrict__ bf,
    const float* __restrict__ Wpa, const float* __restrict__ bpa,
    const float* __restrict__ Wpp, const float* __restrict__ bpp,
    const float* __restrict__ Wrp, const float* __restrict__ brp,
    const float* __restrict__ Wra, const float* __restrict__ bra,
    const float* __restrict__ Wap)
{
    int bt = blockIdx.x;            // 0..799
    int b  = bt / TT;
    int t  = bt % TT;
    int tid = threadIdx.x;

    __shared__ float feat[48];      // mcep[40] | apdc[5] | f0
    __shared__ float hsm[HID];
    __shared__ float cam[COND], cpm[COND];
    __shared__ float mcp[M1], mca[M1];

    if (tid < M1)            feat[tid] = mceps[bt * M1 + tid];
    else if (tid < M1 + A1)  feat[tid] = apdcs[bt * A1 + (tid - M1)];
    else if (tid == 45)      feat[45]  = f0s[bt];
    __syncthreads();

    // hs = mceps@Wm + bm + apdcs@Wa + ba + f0@Wf + bf
    {
        float s = bm[tid] + ba[tid] + bf[tid];
        #pragma unroll 8
        for (int i = 0; i < M1; i++) s = fmaf(feat[i], Wm[i * HID + tid], s);
        #pragma unroll
        for (int i = 0; i < A1; i++) s = fmaf(feat[M1 + i], Wa[i * HID + tid], s);
        s = fmaf(feat[45], Wf[tid], s);
        hsm[tid] = s;
    }
    __syncthreads();

    if (tid < COND) {
        float sa = bpa[tid], sp = bpp[tid];
        #pragma unroll 8
        for (int i = 0; i < HID; i++) {
            float h = hsm[i];
            sa = fmaf(h, Wpa[i * COND + tid], sa);
            sp = fmaf(h, Wpp[i * COND + tid], sp);
        }
        cam[tid] = sa;
        cpm[tid] = sp;
    }
    __syncthreads();

    if (tid < M1) {
        float rp = brp[tid], ra = bra[tid];
        #pragma unroll 8
        for (int i = 0; i < COND; i++) {
            rp = fmaf(cpm[i], Wrp[i * M1 + tid], rp);
            ra = fmaf(cam[i], Wra[i * M1 + tid], ra);
        }
        float apm = 0.f;
        #pragma unroll
        for (int i = 0; i < A1; i++) apm = fmaf(feat[M1 + i], Wap[i * M1 + tid], apm);
        float sp = feat[tid];                          // mcep (denorm is identity)
        mcp[tid] = sp + 0.1f * tanhf(rp);
        mca[tid] = sp + 0.1f * tanhf(ra) + apm;
    }
    __syncthreads();

    // mc2b (serial scan over order, high->low): b_m = c_m - alpha*b_{m+1}
    if (tid < 2) {
        const float* mc = (tid == 0) ? mcp : mca;
        int ch = (tid == 0) ? b : (4 + b);
        float* dst = g_bcoef + (ch * TT + t) * M1;
        float bbv = 0.f, b1v = 0.f;
        #pragma unroll
        for (int m = M1 - 1; m >= 0; m--) {
            bbv = fmaf(-ALPHA, bbv, mc[m]);
            dst[m] = bbv;
            if (m == 1) b1v = bbv;
        }
        g_eb0[ch * TT + t] = expf(bbv);    // bbv now holds b[0]
        g_b1[ch * TT + t]  = b1v;
        if (tid == 0) g_f0[b * TT + t] = expf(fmaf(feat[45], 0.25f, 5.0f));
    }
}

// ==================================================================
// K2: pulse-train excitation.
// Phase = cumsum(f0_up/SR) replicated BIT-EXACTLY as JAX's
// lax.associative_scan(add) odd/even recursive tree (the lowering of
// jnp.cumsum on non-TPU backends):
//   up-sweep  : r[i] = x[2i] + x[2i+1]   (unpaired tail element dropped)
//   down-sweep: scan[2i+1] = s+[i];  scan[0] = x[0];
//               scan[2i]   = s+[i-1] + x[2i]   (i >= 1)
// All f32 RN in this exact order -> bit-identical phase -> bit-identical
// floor-crossing pulse positions.
// One block per batch; levels in global scratch.
// ==================================================================
__global__ __launch_bounds__(256) void k_pulse()
{
    const int b   = blockIdx.x;
    const int tid = threadIdx.x;
    const int NTH = blockDim.x;

    const int ln[15] = {24000,12000,6000,3000,1500,750,375,187,93,46,23,11,5,2,1};
    int off[15];
    off[0] = 0;
    #pragma unroll
    for (int k = 1; k < 15; k++) off[k] = off[k-1] + ln[k-1];

    float* buf = g_scanbuf + b * SCAN_TOTAL;

    // level 0: inc[i] = f0_up[i] / SR
    for (int i = tid; i < NN; i += NTH)
        buf[i] = g_f0[b * TT + i / HOP] / SRF;
    __syncthreads();

    // up-sweep
    for (int k = 0; k < 14; k++) {
        const float* src = buf + off[k];
        float*       dst = buf + off[k+1];
        const int nn1 = ln[k+1];
        for (int i = tid; i < nn1; i += NTH)
            dst[i] = src[2*i] + src[2*i+1];
        __syncthreads();
    }

    // down-sweep (in place: level k array becomes its own inclusive scan)
    for (int k = 13; k >= 0; k--) {
        float*       a = buf + off[k];
        const float* s = buf + off[k+1];
        const int n = ln[k];
        for (int i = tid; i < n; i += NTH) {
            float v;
            if (i & 1)            v = s[i >> 1];
            else if (i == 0)      v = a[0];
            else                  v = s[(i >> 1) - 1] + a[i];
            a[i] = v;
        }
        __syncthreads();
    }

    // pulses: w[i] = floor(phase[i]); fire when w > w_prev (w_prev[0] = 0)
    for (int i = tid; i < NN; i += NTH) {
        float w  = floorf(buf[i]);
        float wp = (i == 0) ? 0.f : floorf(buf[i-1]);
        float f  = g_f0[b * TT + i / HOP];
        float amp = 0.5f * sqrtf(SRF / fmaxf(f, 1.0f));   // * (1 - NOISE_RATIO)
        g_exc[b * NN + i] = (w > wp) ? amp : 0.f;
    }
}

// ==================================================================
// K3: MLSA synthesis filter scan — ONE WARP PER CHANNEL.
//   lanes 0..3 : stage-2 Pade tap p = lane (38-reg delay line, SIMT lockstep)
//   all lanes  : stage-1 filter replicated (y1 in-register everywhere)
//   exchange   : 4x shfl.idx gather + redundant Pade reduce on all lanes
// No __syncthreads, no shared memory, no divergent branches in hot loop.
// Order recurrence re-associated: new_m = (n[m-1] + a*n[m]) - a*new_{m-1}
// -> 1 dependent FMA (4 cyc) per order step.
// ==================================================================
__global__ __launch_bounds__(32, 1) void k_mlsa(const float* __restrict__ noise)
{
    const int c    = blockIdx.x;          // channel
    const int lane = threadIdx.x;         // 0..31 (taps on 0..3)

    // ---- stage-2 tap state (meaningful on lanes 0..3) ----
    float n[38];
    #pragma unroll
    for (int j = 0; j < 38; j++) n[j] = 0.f;
    float breg[38];
    float d1o = 0.f, xin = 0.f;

    // ---- stage-1 state (replicated, identical on every lane) ----
    float x1p = 0.f, npt0 = 0.f, npt1 = 0.f, npt2 = 0.f;
    float na0 = 0.f, na1 = 0.f, na2 = 0.f, na3 = 0.f;

    const float* bc  = g_bcoef + c * TT * M1;
    const bool periodic = (c < 4);
    const float* src = periodic ? (g_exc + c * NN) : (noise + (c - 4) * NN);
    const float scl  = periodic ? 1.0f : 0.5f;
    float* wout = g_wav + c * NN;

    float excv = src[0] * scl;            // prefetch sample 0

    for (int fr = 0; fr < TT; fr++) {
        const float* bf_ = bc + fr * M1;
        const float eb0 = g_eb0[c * TT + fr];
        const float b1  = g_b1[c * TT + fr];
        #pragma unroll
        for (int j = 0; j < 38; j++) breg[j] = bf_[2 + j];   // broadcast loads

        const int base = fr * HOP;
        for (int j = 0; j < HOP; j++) {
            const int i = base + j;

            // ---- stage-1 (mlsadf1), replicated on all lanes ----
            float x  = excv * eb0;
            float m0 = fmaf(ALPHA, na0, AAC * x1p);
            float m1 = fmaf(ALPHA, na1, AAC * npt0);
            float m2 = fmaf(ALPHA, na2, AAC * npt1);
            float m3 = fmaf(ALPHA, na3, AAC * npt2);
            na0 = m0; na1 = m1; na2 = m2; na3 = m3;
            float p0 = m0 * b1, p1 = m1 * b1, p2 = m2 * b1, p3 = m3 * b1;
            float sA1 = fmaf(P3C, p2, P1C * p0);
            float sB1 = fmaf(P4C, p3, P2C * p1);
            float x1 = x + (sA1 - sB1);
            float y1 = x1 + (sA1 + sB1);
            x1p = x1; npt0 = p0; npt1 = p1; npt2 = p2;

            // prefetch next excitation sample (off critical path)
            if (i + 1 < NN) excv = src[i + 1] * scl;

            // ---- stage-2 tap (mlsafir order recurrence), lane = tap ----
            float d1n = fmaf(ALPHA, d1o, AAC * xin);
            float pm1 = n[0];
            float nw  = fmaf(-ALPHA, d1n, fmaf(ALPHA, n[0], d1o));
            float y   = nw * breg[0];
            n[0] = nw;
            #pragma unroll
            for (int m = 1; m < 38; m++) {
                float cc = fmaf(ALPHA, n[m], pm1);   // off-chain
                pm1 = n[m];
                nw  = fmaf(-ALPHA, nw, cc);          // 4-cyc chain
                y   = fmaf(nw, breg[m], y);          // off-chain accum
                n[m] = nw;
            }
            d1o = d1n;

            // ---- cross-tap exchange + Pade reduce (all lanes, converged) ----
            float t0 = __shfl_sync(0xffffffffu, y, 0);
            float t1 = __shfl_sync(0xffffffffu, y, 1);
            float t2 = __shfl_sync(0xffffffffu, y, 2);
            float t3 = __shfl_sync(0xffffffffu, y, 3);
            float sA = fmaf(P3C, t2, P1C * t0);
            float sB = fmaf(P4C, t3, P2C * t1);
            float x2 = y1 + (sA - sB);
            float y2 = x2 + (sA + sB);
            if (lane == 0) wout[i] = y2;             // predicated store

            // next-sample tap inputs: pt2 = [x2, fy0, fy1, fy2]
            float up = __shfl_up_sync(0xffffffffu, y, 1);
            xin = (lane == 0) ? x2 : up;
        }
    }
}

// ==================================================================
// K4: sum periodic + aperiodic channels into output
// ==================================================================
__global__ void k_sum(float* __restrict__ out)
{
    int i = blockIdx.x * 256 + threadIdx.x;
    if (i < BB * NN) out[i] = g_wav[i] + g_wav[BB * NN + i];
}

// ==================================================================
extern "C" void kernel_launch(void* const* d_in, const int* in_sizes, int n_in,
                              void* d_out, int out_size)
{
    const float* mceps = (const float*)d_in[0];
    const float* apdcs = (const float*)d_in[1];
    const float* f0s   = (const float*)d_in[2];
    const float* noise = (const float*)d_in[3];
    const float* Wm  = (const float*)d_in[4];
    const float* bm  = (const float*)d_in[5];
    const float* Wa  = (const float*)d_in[6];
    const float* ba  = (const float*)d_in[7];
    const float* Wf  = (const float*)d_in[8];
    const float* bf  = (const float*)d_in[9];
    const float* Wpa = (const float*)d_in[10];
    const float* bpa = (const float*)d_in[11];
    const float* Wpp = (const float*)d_in[12];
    const float* bpp = (const float*)d_in[13];
    const float* Wrp = (const float*)d_in[14];
    const float* brp = (const float*)d_in[15];
    const float* Wra = (const float*)d_in[16];
    const float* bra = (const float*)d_in[17];
    const float* Wap = (const float*)d_in[18];

    k_frontend<<<BB * TT, 256>>>(mceps, apdcs, f0s,
                                 Wm, bm, Wa, ba, Wf, bf,
                                 Wpa, bpa, Wpp, bpp,
                                 Wrp, brp, Wra, bra, Wap);
    k_pulse<<<BB, 256>>>();
    k_mlsa<<<NCH, 32>>>(noise);
    k_sum<<<(BB * NN + 255) / 256, 256>>>((float*)d_out);
}